// round 2
// baseline (speedup 1.0000x reference)
#include <cuda_runtime.h>
#include <math.h>

// Problem constants (fixed shapes from reference setup_inputs):
//   input:  (B=2, T=2048, V=32000) float32
//   target: (B=2, T=2048) int32  (JAX demotes int64 -> int32 without x64 mode)
//   output: scalar float32
// CT_LENGTH=0.25 -> ct_len = 512 ; PRECED_M_NEGATIVES=0.5 -> win = 256
#define B_DIM 2
#define T_DIM 2048
#define V_DIM 32000
#define CT_LEN 512
#define WIN 256
#define ROWS (B_DIM * CT_LEN)
#define IGNORE_INDEX (-100)
#define PAD_ID 0

// Allocation-free scratch (deterministic: every element rewritten each call)
__device__ float g_row_loss[ROWS];
__device__ int   g_row_valid[ROWS];

// One CTA per (b, i) row. 256 threads, thread k handles negative j = i - WIN + k.
__global__ __launch_bounds__(WIN, 8)
void ctl_row_kernel(const float* __restrict__ input,
                    const int* __restrict__ target)
{
    const int row = blockIdx.x;           // b * CT_LEN + i
    const int b   = row >> 9;             // / CT_LEN (512)
    const int i   = row & (CT_LEN - 1);
    const int tid = threadIdx.x;

    const int tbase = b * T_DIM;                                 // target row base
    const long long lbase = ((long long)b * T_DIM + i) * V_DIM;  // logits row base

    __shared__ float s_pos;
    __shared__ int   s_valid;
    if (tid == 0) {
        int t = target[tbase + i];
        int valid = (t != IGNORE_INDEX);
        int ts = valid ? t : PAD_ID;   // tgt_safe
        ts = ts < 0 ? 0 : (ts >= V_DIM ? V_DIM - 1 : ts);  // defensive clamp
        s_valid = valid;
        s_pos = input[lbase + ts];
    }
    __syncthreads();

    const float pos  = s_pos;
    const int   vrow = s_valid;

    // Negative term for this thread's j
    float e = 0.0f;
    const int j = i - WIN + tid;            // j in [i-WIN, i)
    if (vrow && j >= 0) {
        int tj = target[tbase + j];
        if (tj != PAD_ID) {                 // valid_neg: prec != PAD_ID
            int idx = tj < 0 ? 0 : (tj >= V_DIM ? V_DIM - 1 : tj);
            e = __expf(input[lbase + idx] - pos);
        }
    }

    // Block reduction: warp shuffles + shared partials
    #pragma unroll
    for (int o = 16; o > 0; o >>= 1)
        e += __shfl_down_sync(0xffffffffu, e, o);

    __shared__ float s_part[WIN / 32];
    if ((tid & 31) == 0) s_part[tid >> 5] = e;
    __syncthreads();

    if (tid == 0) {
        float sum = 0.0f;
        #pragma unroll
        for (int w = 0; w < WIN / 32; w++) sum += s_part[w];
        g_row_loss[row]  = vrow ? log1pf(sum) : 0.0f;
        g_row_valid[row] = vrow;
    }
}

// Single-block final reduction over 1024 rows -> scalar mean
__global__ __launch_bounds__(ROWS, 1)
void ctl_finish_kernel(float* __restrict__ out)
{
    const int tid = threadIdx.x;
    float l = g_row_loss[tid];
    float v = (float)g_row_valid[tid];

    #pragma unroll
    for (int o = 16; o > 0; o >>= 1) {
        l += __shfl_down_sync(0xffffffffu, l, o);
        v += __shfl_down_sync(0xffffffffu, v, o);
    }

    __shared__ float sl[ROWS / 32];
    __shared__ float sv[ROWS / 32];
    if ((tid & 31) == 0) { sl[tid >> 5] = l; sv[tid >> 5] = v; }
    __syncthreads();

    if (tid < 32) {
        float l2 = (tid < ROWS / 32) ? sl[tid] : 0.0f;
        float v2 = (tid < ROWS / 32) ? sv[tid] : 0.0f;
        #pragma unroll
        for (int o = 16; o > 0; o >>= 1) {
            l2 += __shfl_down_sync(0xffffffffu, l2, o);
            v2 += __shfl_down_sync(0xffffffffu, v2, o);
        }
        if (tid == 0) {
            float denom = fmaxf(v2, 1.0f);
            out[0] = l2 / denom;
        }
    }
}

extern "C" void kernel_launch(void* const* d_in, const int* in_sizes, int n_in,
                              void* d_out, int out_size)
{
    const float* input  = (const float*)d_in[0];
    const int*   target = (const int*)d_in[1];
    float*       out    = (float*)d_out;

    (void)in_sizes; (void)n_in; (void)out_size;

    ctl_row_kernel<<<ROWS, WIN>>>(input, target);
    ctl_finish_kernel<<<1, ROWS>>>(out);
}

// round 4
// speedup vs baseline: 1.0257x; 1.0257x over previous
#include <cuda_runtime.h>
#include <math.h>

// Problem constants (fixed shapes from reference setup_inputs):
//   input:  (B=2, T=2048, V=32000) float32
//   target: (B=2, T=2048) int32  (JAX default: int64 demoted to int32)
//   output: scalar float32
// CT_LENGTH=0.25 -> ct_len = 512 ; PRECED_M_NEGATIVES=0.5 -> win = 256
#define B_DIM 2
#define T_DIM 2048
#define V_DIM 32000
#define CT_LEN 512
#define WIN 256
#define ROWS (B_DIM * CT_LEN)
#define IGNORE_INDEX (-100)
#define PAD_ID 0

// Allocation-free scratch (every element rewritten each call; counter self-resets)
__device__ float        g_row_loss[ROWS];
__device__ float        g_row_valid[ROWS];
__device__ unsigned int g_done = 0u;

// One CTA per (b, i) row. 256 threads, thread k handles negative j = i - WIN + k.
// The last CTA to finish performs the final mean and writes the scalar output.
__global__ __launch_bounds__(WIN, 8)
void ctl_fused_kernel(const float* __restrict__ input,
                      const int* __restrict__ target,
                      float* __restrict__ out)
{
    const int row = blockIdx.x;           // b * CT_LEN + i
    const int b   = row >> 9;             // / CT_LEN (512)
    const int i   = row & (CT_LEN - 1);
    const int tid = threadIdx.x;

    const int tbase = b * T_DIM;                                 // target row base
    const long long lbase = ((long long)b * T_DIM + i) * V_DIM;  // logits row base

    // --- Issue ALL loads up front, no serialization ---
    // Positive: same address for every thread -> broadcast/L1-hit, 1 DRAM sector.
    const int t     = target[tbase + i];
    const int vrow  = (t != IGNORE_INDEX);
    int ts          = vrow ? t : PAD_ID;                 // tgt_safe
    ts = ts < 0 ? 0 : (ts >= V_DIM ? V_DIM - 1 : ts);    // defensive clamp

    // Negative: thread's own j. Load unconditionally when in-band (idx clamped),
    // so the gather is in flight concurrently with the pos load.
    const int j = i - WIN + tid;                         // j in [i-WIN, i)
    int   neg_ok = 0;
    float negv   = 0.0f;
    float pos;
    {
        int tj = (j >= 0) ? target[tbase + j] : PAD_ID;
        neg_ok = (j >= 0) & (tj != PAD_ID);
        int idx = tj < 0 ? 0 : (tj >= V_DIM ? V_DIM - 1 : tj);
        pos = input[lbase + ts];                         // in flight
        if (neg_ok) negv = input[lbase + idx];           // in flight concurrently
    }

    float e = (neg_ok && vrow) ? __expf(negv - pos) : 0.0f;

    // --- Block reduction: warp shuffles + shared partials ---
    #pragma unroll
    for (int o = 16; o > 0; o >>= 1)
        e += __shfl_down_sync(0xffffffffu, e, o);

    __shared__ float s_part[WIN / 32];
    if ((tid & 31) == 0) s_part[tid >> 5] = e;
    __syncthreads();

    __shared__ int s_last;
    if (tid == 0) {
        float sum = 0.0f;
        #pragma unroll
        for (int w = 0; w < WIN / 32; w++) sum += s_part[w];
        g_row_loss[row]  = vrow ? log1pf(sum) : 0.0f;
        g_row_valid[row] = (float)vrow;
        __threadfence();                                  // make row result visible
        unsigned int ticket = atomicAdd(&g_done, 1u);
        s_last = (ticket == (unsigned int)(ROWS - 1));
    }
    __syncthreads();

    // --- Last CTA: final reduction over all rows (fixed order -> deterministic) ---
    if (s_last) {
        float l = 0.0f, v = 0.0f;
        #pragma unroll
        for (int k = 0; k < ROWS / WIN; k++) {
            l += g_row_loss[tid + k * WIN];
            v += g_row_valid[tid + k * WIN];
        }
        #pragma unroll
        for (int o = 16; o > 0; o >>= 1) {
            l += __shfl_down_sync(0xffffffffu, l, o);
            v += __shfl_down_sync(0xffffffffu, v, o);
        }
        __shared__ float sl[WIN / 32];
        __shared__ float sv[WIN / 32];
        if ((tid & 31) == 0) { sl[tid >> 5] = l; sv[tid >> 5] = v; }
        __syncthreads();
        if (tid == 0) {
            float l2 = 0.0f, v2 = 0.0f;
            #pragma unroll
            for (int w = 0; w < WIN / 32; w++) { l2 += sl[w]; v2 += sv[w]; }
            out[0] = l2 / fmaxf(v2, 1.0f);
            g_done = 0u;                                  // reset for next graph replay
        }
    }
}

extern "C" void kernel_launch(void* const* d_in, const int* in_sizes, int n_in,
                              void* d_out, int out_size)
{
    const float* input  = (const float*)d_in[0];
    const int*   target = (const int*)d_in[1];
    float*       out    = (float*)d_out;

    (void)in_sizes; (void)n_in; (void)out_size;

    ctl_fused_kernel<<<ROWS, WIN>>>(input, target, out);
}

// round 5
// speedup vs baseline: 1.0295x; 1.0037x over previous
#include <cuda_runtime.h>
#include <math.h>

// input:  (B=2, T=2048, V=32000) f32 ; target: (2, 2048) int32 ; out: scalar f32
// ct_len = 512, win = 256
#define B_DIM 2
#define T_DIM 2048
#define V_DIM 32000
#define CT_LEN 512
#define WIN 256
#define ROWS (B_DIM * CT_LEN)      // 1024
#define IGNORE_INDEX (-100)
#define PAD_ID 0

#define WARPS_PER_CTA 8
#define CTA_THREADS (WARPS_PER_CTA * 32)      // 256
#define GRID_CTAS (ROWS / WARPS_PER_CTA)      // 128
#define NEGS_PER_LANE (WIN / 32)              // 8

// Allocation-free scratch (every element rewritten each call; counter self-resets)
__device__ float        g_row_loss[ROWS];
__device__ float        g_row_valid[ROWS];
__device__ unsigned int g_done = 0u;

__global__ __launch_bounds__(CTA_THREADS, 8)
void ctl_warp_kernel(const float* __restrict__ input,
                     const int* __restrict__ target,
                     float* __restrict__ out)
{
    const int tid  = threadIdx.x;
    const int lane = tid & 31;
    const int w    = tid >> 5;
    const int row  = blockIdx.x * WARPS_PER_CTA + w;  // 0..1023
    const int b    = row >> 9;                        // / CT_LEN
    const int i    = row & (CT_LEN - 1);

    const int tbase = b * T_DIM;
    const long long lbase = ((long long)(b * T_DIM + i)) * V_DIM;

    // --- batch 1: all target loads (coalesced) + row target (broadcast) ---
    const int t    = __ldg(&target[tbase + i]);
    int tj[NEGS_PER_LANE];
    #pragma unroll
    for (int k = 0; k < NEGS_PER_LANE; k++) {
        const int j = i - WIN + k * 32 + lane;
        tj[k] = (j >= 0) ? __ldg(&target[tbase + j]) : PAD_ID;
    }

    const int vrow = (t != IGNORE_INDEX);
    int ts = vrow ? t : PAD_ID;
    ts = ts < 0 ? 0 : (ts >= V_DIM ? V_DIM - 1 : ts);

    // --- batch 2: pos (warp-broadcast) + 8 independent gathers, all in flight ---
    const float pos = __ldg(&input[lbase + ts]);
    float nv[NEGS_PER_LANE];
    #pragma unroll
    for (int k = 0; k < NEGS_PER_LANE; k++) {
        int c = tj[k];
        int idx = c < 0 ? 0 : (c >= V_DIM ? V_DIM - 1 : c);  // PAD/j<0 -> idx 0 (broadcast, cheap)
        nv[k] = __ldg(&input[lbase + idx]);
    }

    // --- compute + warp reduction (no shared, no barriers) ---
    float e = 0.0f;
    #pragma unroll
    for (int k = 0; k < NEGS_PER_LANE; k++) {
        if (tj[k] != PAD_ID)                      // j<0 lanes have tj==PAD -> excluded
            e += __expf(nv[k] - pos);
    }
    #pragma unroll
    for (int o = 16; o > 0; o >>= 1)
        e += __shfl_down_sync(0xffffffffu, e, o);

    if (lane == 0) {
        g_row_loss[row]  = vrow ? log1pf(e) : 0.0f;
        g_row_valid[row] = (float)vrow;
    }

    // --- last-CTA final reduction ---
    __shared__ int s_last;
    __syncthreads();
    if (tid == 0) {
        __threadfence();
        unsigned int ticket = atomicAdd(&g_done, 1u);
        s_last = (ticket == (unsigned int)(GRID_CTAS - 1));
    }
    __syncthreads();

    if (s_last) {
        float l = 0.0f, v = 0.0f;
        #pragma unroll
        for (int k = 0; k < ROWS / CTA_THREADS; k++) {
            l += g_row_loss[tid + k * CTA_THREADS];
            v += g_row_valid[tid + k * CTA_THREADS];
        }
        #pragma unroll
        for (int o = 16; o > 0; o >>= 1) {
            l += __shfl_down_sync(0xffffffffu, l, o);
            v += __shfl_down_sync(0xffffffffu, v, o);
        }
        __shared__ float sl[CTA_THREADS / 32];
        __shared__ float sv[CTA_THREADS / 32];
        if (lane == 0) { sl[w] = l; sv[w] = v; }
        __syncthreads();
        if (tid == 0) {
            float l2 = 0.0f, v2 = 0.0f;
            #pragma unroll
            for (int q = 0; q < CTA_THREADS / 32; q++) { l2 += sl[q]; v2 += sv[q]; }
            out[0] = l2 / fmaxf(v2, 1.0f);
            g_done = 0u;                       // reset for next graph replay
        }
    }
}

extern "C" void kernel_launch(void* const* d_in, const int* in_sizes, int n_in,
                              void* d_out, int out_size)
{
    const float* input  = (const float*)d_in[0];
    const int*   target = (const int*)d_in[1];
    float*       out    = (float*)d_out;

    (void)in_sizes; (void)n_in; (void)out_size;

    ctl_warp_kernel<<<GRID_CTAS, CTA_THREADS>>>(input, target, out);
}